// round 14
// baseline (speedup 1.0000x reference)
#include <cuda_runtime.h>
#include <math.h>

#define Bn 8
#define Cn 64
#define On 64
#define Hn 128
#define Wn 128
#define HWn 16384
#define KKn 9
#define WR2 9           // x-window rows staged in smem (kernel B, 2-row block)

typedef unsigned long long u64;

// packed dual-fp32 FMA: (lo,hi) elementwise, exact fp32 semantics
__device__ __forceinline__ u64 fma2(u64 a, u64 b, u64 c) {
    u64 d;
    asm("fma.rn.f32x2 %0,%1,%2,%3;" : "=l"(d) : "l"(a), "l"(b), "l"(c));
    return d;
}
__device__ __forceinline__ u64 dup2(float a) {
    u64 d;
    asm("mov.b64 %0,{%1,%1};" : "=l"(d) : "f"(a));
    return d;
}
__device__ __forceinline__ void unpack2(u64 v, float& lo, float& hi) {
    asm("mov.b64 {%0,%1},%2;" : "=f"(lo), "=f"(hi) : "l"(v));
}

// scratch: sigmoid(mask conv) + transposed weights
__device__ float g_mask[Bn * KKn * HWn];
__device__ float g_wT[576 * 64];     // deform weights [kk][o]
__device__ float g_pmT[576 * 36];    // offset+mask weights [kk][o], o>=27 zero

// ---------------------------------------------------------------------------
// Prep: transpose weights so per-chunk smem staging is conflict-free.
// ---------------------------------------------------------------------------
__global__ __launch_bounds__(256) void prep_kernel(
    const float* __restrict__ d_w,
    const float* __restrict__ p_w, const float* __restrict__ m_w)
{
    int e = blockIdx.x * 256 + threadIdx.x;
    if (e < 576 * 64) {
        int kk = e >> 6, o = e & 63;
        g_wT[e] = d_w[o * 576 + kk];
    }
    if (e < 576 * 36) {
        int kk = e / 36, o = e - kk * 36;
        float v = 0.f;
        if (o < 18)      v = p_w[o * 576 + kk];
        else if (o < 27) v = m_w[(o - 18) * 576 + kk];
        g_pmT[e] = v;
    }
}

// ---------------------------------------------------------------------------
// Kernel A: fused 3x3 conv -> 18 offset + 9 mask (sigmoid). (unchanged R13)
// ---------------------------------------------------------------------------
__global__ __launch_bounds__(256) void conv_offmask_kernel(
    const float* __restrict__ x,
    const float* __restrict__ p_b, const float* __restrict__ m_b,
    float* __restrict__ offs_out)
{
    __shared__ float sX[8][4][132];     // 16896 B
    __shared__ float sW[72 * 36];       // 10368 B

    const int h2 = blockIdx.x, b = blockIdx.y;
    const int tid = threadIdx.x;
    const int warp = tid >> 5, lane = tid & 31;
    const int px4 = ((warp & 3) * 8 + (lane & 7)) * 4;
    const int oc  = ((warp >> 2) * 4 + (lane >> 3)) * 4;
    const int i0  = px4 ? (px4 - 1) : 130;

    if (tid < 128) {
        int c = tid >> 4, r = (tid >> 2) & 3, k = tid & 3;
        sX[c][r][128 + k] = 0.f;
    }

    u64 acc2[2][4][2] = {};

    for (int c0 = 0; c0 < Cn; c0 += 8) {
        __syncthreads();
        #pragma unroll
        for (int j = 0; j < 4; ++j) {
            int e = tid + j * 256;
            int cr = e >> 5, q = e & 31;
            int c = cr >> 2, r = cr & 3;
            int y = 2 * h2 - 1 + r;
            float4 v = make_float4(0.f, 0.f, 0.f, 0.f);
            if ((unsigned)y < Hn)
                v = *(const float4*)
                    (x + (((size_t)(b * Cn + c0 + c)) << 14) + y * Wn + q * 4);
            *(float4*)&sX[c][r][q * 4] = v;
        }
        {
            const float4* src = (const float4*)(g_pmT + c0 * 9 * 36);
            for (int e = tid; e < 648; e += 256)
                ((float4*)sW)[e] = src[e];
        }
        __syncthreads();

        #pragma unroll
        for (int c = 0; c < 8; ++c) {
            #pragma unroll
            for (int ki = 0; ki < 3; ++ki) {
                const float* r0 = sX[c][ki];
                const float* r1 = sX[c][ki + 1];
                float4 Xa = *(const float4*)&r0[px4];
                float4 Xb = *(const float4*)&r1[px4];
                float xsA[6] = {r0[i0], Xa.x, Xa.y, Xa.z, Xa.w, r0[px4 + 4]};
                float xsB[6] = {r1[i0], Xb.x, Xb.y, Xb.z, Xb.w, r1[px4 + 4]};
                int kkb = c * 9 + ki * 3;
                #pragma unroll
                for (int kj = 0; kj < 3; ++kj) {
                    float4 wv = *(const float4*)&sW[(kkb + kj) * 36 + oc];
                    u64 wp0 = ((const u64*)&wv)[0];
                    u64 wp1 = ((const u64*)&wv)[1];
                    #pragma unroll
                    for (int r = 0; r < 4; ++r) {
                        u64 aA = dup2(xsA[r + kj]);
                        acc2[0][r][0] = fma2(aA, wp0, acc2[0][r][0]);
                        acc2[0][r][1] = fma2(aA, wp1, acc2[0][r][1]);
                        u64 aB = dup2(xsB[r + kj]);
                        acc2[1][r][0] = fma2(aB, wp0, acc2[1][r][0]);
                        acc2[1][r][1] = fma2(aB, wp1, acc2[1][r][1]);
                    }
                }
            }
        }
    }

    #pragma unroll
    for (int rr = 0; rr < 2; ++rr) {
        int row = (2 * h2 + rr) * Wn;
        float acc[4][4];
        #pragma unroll
        for (int r = 0; r < 4; ++r) {
            unpack2(acc2[rr][r][0], acc[r][0], acc[r][1]);
            unpack2(acc2[rr][r][1], acc[r][2], acc[r][3]);
        }
        #pragma unroll
        for (int q = 0; q < 4; ++q) {
            int o = oc + q;
            if (o < 18) {
                float bias = p_b[o];
                float* dst = offs_out + (((size_t)(b * 18 + o)) << 14) + row;
                float4 v = make_float4(acc[0][q] + bias, acc[1][q] + bias,
                                       acc[2][q] + bias, acc[3][q] + bias);
                *(float4*)&dst[px4] = v;
            } else if (o < 27) {
                float bias = m_b[o - 18];
                float* dst = g_mask + (((size_t)(b * 9 + (o - 18))) << 14) + row;
                float4 v;
                v.x = 1.f / (1.f + expf(-(acc[0][q] + bias)));
                v.y = 1.f / (1.f + expf(-(acc[1][q] + bias)));
                v.z = 1.f / (1.f + expf(-(acc[2][q] + bias)));
                v.w = 1.f / (1.f + expf(-(acc[3][q] + bias)));
                *(float4*)&dst[px4] = v;
            }
        }
    }
}

// ---------------------------------------------------------------------------
// Kernel B: modulated deformable conv, 2-ROW block (256px x 64oc), K-chunk 4.
// Thread tile 8px x 8oc (fma2), conflict-free LDS-window gather, transposed
// conflict-free weight staging. One 9-row x window serves both output rows.
// ---------------------------------------------------------------------------
// smem layout (bytes):
#define SM_SA    0        // 36*256 f    = 36864
#define SM_SW    36864    // 36*64 f     = 9216
#define SM_SPOS  46080    // 2304 short  = 4608
#define SM_SFLAG 50688    // 2304 B      (pad to 52992)
#define SM_SWT   52992    // 2304 f4     = 36864
#define SM_SX    89856    // 4ch*9r*128 f= 18432
#define SM_GUARD 108288   // 258 f       = 1032
#define SM_TOTAL 109320

__global__ __launch_bounds__(256, 2) void deform_kernel(
    const float* __restrict__ x,
    const float* __restrict__ offs,
    const float* __restrict__ d_b,
    float* __restrict__ out)
{
    extern __shared__ char smc[];
    float* sA   = (float*)(smc + SM_SA);
    float* sW   = (float*)(smc + SM_SW);
    short* spos = (short*)(smc + SM_SPOS);
    unsigned char* sflag = (unsigned char*)(smc + SM_SFLAG);
    float4* swt = (float4*)(smc + SM_SWT);
    float* sX   = (float*)(smc + SM_SX);
    float* guard = (float*)(smc + SM_GUARD);

    const int h2 = blockIdx.x, b = blockIdx.y;      // rows hp, hp+1
    const int hp = 2 * h2;
    const int tid = threadIdx.x;
    const int warp = tid >> 5, lane = tid & 31;
    const int px8 = ((warp & 3) * 8 + (lane & 7)) * 8;   // 8 px (0..255)
    const int oc8 = ((warp >> 2) * 4 + (lane >> 3)) * 8; // 8 out channels
    const int ys = min(max(hp - 3, 0), Hn - WR2);        // window start row

    for (int e = tid; e < 258; e += 256) guard[e] = 0.f;

    // precompute per row r (0/1): folded bilinear weights + window index+flag
    for (int e = tid; e < 2 * KKn * Wn; e += 256) {
        int i = e & 127, k = (e >> 7) % KKn, r = e / (KKn * Wn);
        int hrow = hp + r, rowg = hrow * Wn;
        float dy = offs[(((size_t)(b * 18 + 2 * k)) << 14) + rowg + i];
        float dx = offs[(((size_t)(b * 18 + 2 * k + 1)) << 14) + rowg + i];
        float m  = g_mask[(((size_t)(b * 9 + k)) << 14) + rowg + i];
        int ki = k / 3, kj = k - ki * 3;
        float py = (float)(hrow - 1 + ki) + dy;
        float px = (float)(i - 1 + kj) + dx;
        float y0f = floorf(py), x0f = floorf(px);
        float fy = py - y0f, fx = px - x0f;
        int y0 = (int)y0f, x0 = (int)x0f;
        int y1 = y0 + 1, x1 = x0 + 1;
        float vy0 = ((unsigned)y0 < Hn) ? 1.f : 0.f;
        float vy1 = ((unsigned)y1 < Hn) ? 1.f : 0.f;
        float vx0 = ((unsigned)x0 < Wn) ? 1.f : 0.f;
        float vx1 = ((unsigned)x1 < Wn) ? 1.f : 0.f;
        float gy = 1.f - fy, gx = 1.f - fx;
        float4 wq;
        wq.x = gy * gx * m * vy0 * vx0;
        wq.y = gy * fx * m * vy0 * vx1;
        wq.z = fy * gx * m * vy1 * vx0;
        wq.w = fy * fx * m * vy1 * vx1;
        int f0 = (y0 < 0) | (y0 > Hn - 1) | ((y0 >= ys) & (y0 <= ys + WR2 - 1));
        int f1 = (y1 < 0) | (y1 > Hn - 1) | ((y1 >= ys) & (y1 <= ys + WR2 - 1));
        int rr = min(max(y0 - ys, -1), WR2);      // garbage-safe clamp
        int xb = min(max(x0, -1), Wn);
        spos[e]  = (short)(rr * Wn + xb);
        swt[e]   = wq;
        sflag[e] = (unsigned char)(f0 & f1);
    }

    const int px_g = tid & 127;         // gather: this thread's pixel (col)
    const int rsel = tid >> 7;          // gather: which output row (0/1)
    const int ebase = rsel * (KKn * Wn);

    u64 acc2[8][4] = {};                // [px][oc-pair]

    for (int c0 = 0; c0 < Cn; c0 += 4) {
        __syncthreads();   // prev GEMM done (and precompute done on iter 0)
        // weights: contiguous float4 copy from transposed gmem (36kk x 64oc)
        {
            const float4* src = (const float4*)(g_wT + c0 * 9 * 64);
            #pragma unroll
            for (int j = 0; j < 3; ++j) {
                int e = tid + j * 256;
                if (e < 576) ((float4*)sW)[e] = src[e];
            }
        }
        // stage 9-row x window for 4 channels (1152 float4, 288/ch)
        for (int e = tid; e < 1152; e += 256) {
            int c = e / 288, rem = e - c * 288;
            const float4* src = (const float4*)
                (x + (((size_t)(b * Cn + c0 + c)) << 14) + ys * Wn) + rem;
            ((float4*)sX)[c * 288 + rem] = *src;
        }
        __syncthreads();

        // gather: thread = (row, pixel), 4 channels; conflict-free LDS
        {
            const float* pg = x + (((size_t)(b * Cn + c0)) << 14);
            const int rowg = (hp + rsel) * Wn;
            #pragma unroll
            for (int t = 0; t < KKn; ++t) {
                int   p0 = spos[ebase + t * 128 + px_g];
                float4 w4 = swt[ebase + t * 128 + px_g];
                int fast = sflag[ebase + t * 128 + px_g];
                if (__all_sync(0xffffffffu, fast)) {
                    #pragma unroll
                    for (int c = 0; c < 4; ++c) {
                        const float* s = sX + c * (WR2 * Wn);
                        float v = w4.x * s[p0]       + w4.y * s[p0 + 1]
                                + w4.z * s[p0 + 128] + w4.w * s[p0 + 129];
                        sA[(c * 9 + t) * 256 + rsel * 128 + px_g] = v;
                    }
                } else {
                    float dy = offs[(((size_t)(b * 18 + 2 * t)) << 14) + rowg + px_g];
                    float dx = offs[(((size_t)(b * 18 + 2 * t + 1)) << 14) + rowg + px_g];
                    int ki = t / 3, kj = t - ki * 3;
                    float py = (float)(hp + rsel - 1 + ki) + dy;
                    float px = (float)(px_g - 1 + kj) + dx;
                    int y0 = (int)floorf(py), x0 = (int)floorf(px);
                    int ry0 = min(max(y0, 0), Hn - 1) * Wn;
                    int ry1 = min(max(y0 + 1, 0), Hn - 1) * Wn;
                    int cx0 = min(max(x0, 0), Wn - 1);
                    int cx1 = min(max(x0 + 1, 0), Wn - 1);
                    int q0 = ry0 + cx0, q1 = ry0 + cx1;
                    int q2 = ry1 + cx0, q3 = ry1 + cx1;
                    #pragma unroll
                    for (int c = 0; c < 4; ++c) {
                        const float* p = pg + c * HWn;
                        float v = w4.x * __ldg(p + q0) + w4.y * __ldg(p + q1)
                                + w4.z * __ldg(p + q2) + w4.w * __ldg(p + q3);
                        sA[(c * 9 + t) * 256 + rsel * 128 + px_g] = v;
                    }
                }
            }
        }
        __syncthreads();

        #pragma unroll 4
        for (int kk = 0; kk < 36; ++kk) {
            float4 a0 = *(const float4*)&sA[kk * 256 + px8];
            float4 a1 = *(const float4*)&sA[kk * 256 + px8 + 4];
            float4 w0 = *(const float4*)&sW[kk * 64 + oc8];
            float4 w1 = *(const float4*)&sW[kk * 64 + oc8 + 4];
            u64 wp[4] = {((const u64*)&w0)[0], ((const u64*)&w0)[1],
                         ((const u64*)&w1)[0], ((const u64*)&w1)[1]};
            float ar[8] = {a0.x, a0.y, a0.z, a0.w, a1.x, a1.y, a1.z, a1.w};
            #pragma unroll
            for (int r = 0; r < 8; ++r) {
                u64 ad = dup2(ar[r]);
                #pragma unroll
                for (int p = 0; p < 4; ++p)
                    acc2[r][p] = fma2(ad, wp[p], acc2[r][p]);
            }
        }
    }

    // epilogue: 8px x 8oc per thread
    const int orow = (hp + (px8 >> 7)) * Wn + (px8 & 127);
    #pragma unroll
    for (int p = 0; p < 4; ++p) {
        float b0 = __ldg(d_b + oc8 + 2 * p);
        float b1 = __ldg(d_b + oc8 + 2 * p + 1);
        float lo[8], hi[8];
        #pragma unroll
        for (int r = 0; r < 8; ++r) unpack2(acc2[r][p], lo[r], hi[r]);
        float* d0 = out + (((size_t)(b * On + oc8 + 2 * p)) << 14) + orow;
        float* d1 = out + (((size_t)(b * On + oc8 + 2 * p + 1)) << 14) + orow;
        *(float4*)d0 = make_float4(lo[0] + b0, lo[1] + b0, lo[2] + b0, lo[3] + b0);
        *(float4*)(d0 + 4) = make_float4(lo[4] + b0, lo[5] + b0, lo[6] + b0, lo[7] + b0);
        *(float4*)d1 = make_float4(hi[0] + b1, hi[1] + b1, hi[2] + b1, hi[3] + b1);
        *(float4*)(d1 + 4) = make_float4(hi[4] + b1, hi[5] + b1, hi[6] + b1, hi[7] + b1);
    }
}

// ---------------------------------------------------------------------------

extern "C" void kernel_launch(void* const* d_in, const int* in_sizes, int n_in,
                              void* d_out, int out_size) {
    const float* x    = (const float*)d_in[0];
    const float* p_w  = (const float*)d_in[1];
    const float* p_b  = (const float*)d_in[2];
    const float* m_w  = (const float*)d_in[3];
    const float* m_b  = (const float*)d_in[4];
    const float* d_wp = (const float*)d_in[5];
    const float* d_bp = (const float*)d_in[6];

    float* out = (float*)d_out;                         // [8,64,128,128]
    float* offs_out = out + (size_t)Bn * On * HWn;      // [8,18,128,128]

    cudaFuncSetAttribute(deform_kernel,
                         cudaFuncAttributeMaxDynamicSharedMemorySize, SM_TOTAL);

    prep_kernel<<<144, 256>>>(d_wp, p_w, m_w);
    dim3 gridA(Hn / 2, Bn);
    dim3 gridB(Hn / 2, Bn);
    conv_offmask_kernel<<<gridA, 256>>>(x, p_b, m_b, offs_out);
    deform_kernel<<<gridB, 256, SM_TOTAL>>>(x, offs_out, d_bp, out);
}